// round 1
// baseline (speedup 1.0000x reference)
#include <cuda_runtime.h>
#include <cstdint>

#define Bn 64
#define Fn 64
#define Cn 8
#define Sn 128
#define Pn (Sn * Sn)          // 16384 pixels per image
#define Kn 10                 // steps_to_run (fixed by setup_inputs)

// Scratch (device globals: allocation-free per harness rules)
__device__ float g_colour[(size_t)Bn * Cn * Pn];  // [b][c][p]  33.5 MB
__device__ float g_logs[(size_t)Bn * Pn];         // [b][p]      4 MB
__device__ float g_seed[Bn * Cn];                 // [b][c]

// ---------------------------------------------------------------------------
// Kernel 1: 1x1 conv + gate + coordinate channels -> g_colour; zero g_logs.
// Each thread produces 4 consecutive pixels (float4) for all 8 channels.
// ---------------------------------------------------------------------------
__global__ void conv_kernel(const float4* __restrict__ feat,
                            const float* __restrict__ w,
                            const float* __restrict__ bias,
                            const float* __restrict__ gate) {
    __shared__ float ws[Cn * Fn];
    __shared__ float bs[Cn];
    int tid = threadIdx.x;
    for (int i = tid; i < Cn * Fn; i += blockDim.x) ws[i] = w[i];
    if (tid < Cn) bs[tid] = bias[tid];
    __syncthreads();

    int gidx = blockIdx.x * blockDim.x + tid;   // 0 .. B*P/4-1  (262144)
    int b = gidx >> 12;                          // P/4 = 4096 float4s per image
    int q = gidx & 4095;                         // float4 index within image

    const float4* fb = feat + (size_t)b * (Fn * Pn / 4) + q;

    float4 acc[Cn];
#pragma unroll
    for (int c = 0; c < Cn; c++) {
        float bb = bs[c];
        acc[c] = make_float4(bb, bb, bb, bb);
    }

#pragma unroll 8
    for (int f = 0; f < Fn; f++) {
        float4 v = fb[(size_t)f * (Pn / 4)];
#pragma unroll
        for (int c = 0; c < Cn; c++) {
            float wc = ws[c * Fn + f];
            acc[c].x += v.x * wc;
            acc[c].y += v.y * wc;
            acc[c].z += v.z * wc;
            acc[c].w += v.w * wc;
        }
    }

    float g = gate[0];
#pragma unroll
    for (int c = 0; c < Cn; c++) {
        acc[c].x *= g; acc[c].y *= g; acc[c].z *= g; acc[c].w *= g;
    }

    // coordinate channels: c==6 -> yy = lin(row), c==7 -> xx = lin(col)
    int p0 = q << 2;              // first pixel of the 4
    int h  = p0 >> 7;             // row
    int wc0 = p0 & 127;           // col of .x
    const float step = 2.0f / 127.0f;
    float yy = -1.0f + step * (float)h;
    acc[6].x += yy; acc[6].y += yy; acc[6].z += yy; acc[6].w += yy;
    float xx = -1.0f + step * (float)wc0;
    acc[7].x += xx;
    acc[7].y += xx + step;
    acc[7].z += xx + 2.0f * step;
    acc[7].w += xx + 3.0f * step;

    float4* cb = (float4*)g_colour;
#pragma unroll
    for (int c = 0; c < Cn; c++)
        cb[((size_t)b * Cn + c) * (Pn / 4) + q] = acc[c];

    // init log-scope to 0
    ((float4*)g_logs)[gidx] = make_float4(0.f, 0.f, 0.f, 0.f);
}

// ---------------------------------------------------------------------------
// Kernel 2: per-batch argmax of rand_pixel * exp(log_s); gather seed colour.
// One block per batch. First-index tie-breaking matches jnp.argmax.
// ---------------------------------------------------------------------------
__global__ void argmax_kernel(const float* __restrict__ rp, int first) {
    const int b = blockIdx.x;
    const int tid = threadIdx.x;                 // blockDim = 512
    const float* rpb = rp + (size_t)b * Pn;
    const float* lsb = g_logs + (size_t)b * Pn;

    float bv = -1e30f;
    int bi = 0;
    for (int p = tid; p < Pn; p += 512) {
        float v = rpb[p];
        if (!first) v *= expf(lsb[p]);
        if (v > bv) { bv = v; bi = p; }          // increasing p: '>' keeps first idx
    }
    // warp reduce (value desc, index asc on ties)
#pragma unroll
    for (int o = 16; o; o >>= 1) {
        float ov = __shfl_down_sync(0xFFFFFFFFu, bv, o);
        int   oi = __shfl_down_sync(0xFFFFFFFFu, bi, o);
        if (ov > bv || (ov == bv && oi < bi)) { bv = ov; bi = oi; }
    }
    __shared__ float sv[16];
    __shared__ int   si[16];
    int wid = tid >> 5;
    if ((tid & 31) == 0) { sv[wid] = bv; si[wid] = bi; }
    __syncthreads();
    if (tid == 0) {
#pragma unroll
        for (int i = 1; i < 16; i++)
            if (sv[i] > bv || (sv[i] == bv && si[i] < bi)) { bv = sv[i]; bi = si[i]; }
#pragma unroll
        for (int c = 0; c < Cn; c++)
            g_seed[b * Cn + c] = g_colour[((size_t)b * Cn + c) * Pn + bi];
    }
}

// ---------------------------------------------------------------------------
// Kernel 3: mask update. One thread per pixel.
//   alpha = clamp(exp(-dist2/sigma)); out[...,k] = log_s + log(alpha);
//   log_s += log(1-alpha); (last step also writes out[...,K])
// ---------------------------------------------------------------------------
__global__ void step_kernel(float* __restrict__ out,
                            const float* __restrict__ log_sigma,
                            int k, int first, int last) {
    int idx = blockIdx.x * blockDim.x + threadIdx.x;  // 0 .. B*P-1
    int b = idx >> 14;
    int p = idx & (Pn - 1);

    float seed[Cn];
#pragma unroll
    for (int c = 0; c < Cn; c++) seed[c] = __ldg(&g_seed[b * Cn + c]);

    float ls = first ? 0.0f : g_logs[idx];

    const float* cb = g_colour + (size_t)b * Cn * Pn + p;
    float d2 = 0.0f;
#pragma unroll
    for (int c = 0; c < Cn; c++) {
        float t = cb[(size_t)c * Pn] - seed[c];
        d2 += t * t;
    }

    float sigma = expf(log_sigma[0]);
    float alpha = expf(-(d2 / sigma));
    alpha = fminf(fmaxf(alpha, 0.01f), 0.99f);

    out[(size_t)idx * (Kn + 1) + k] = ls + logf(alpha);
    ls += logf(1.0f - alpha);
    if (last)
        out[(size_t)idx * (Kn + 1) + Kn] = ls;
    else
        g_logs[idx] = ls;
}

// ---------------------------------------------------------------------------
extern "C" void kernel_launch(void* const* d_in, const int* in_sizes, int n_in,
                              void* d_out, int out_size) {
    const float* features  = (const float*)d_in[0];   // [64,64,128,128]
    const float* rand_pix  = (const float*)d_in[1];   // [64,1,128,128]
    const float* conv_w    = (const float*)d_in[2];   // [8,64,1,1]
    const float* conv_b    = (const float*)d_in[3];   // [8]
    const float* gate      = (const float*)d_in[4];   // [1]
    const float* log_sigma = (const float*)d_in[5];   // scalar
    float* out = (float*)d_out;                       // [64,1,128,128,11]

    (void)in_sizes; (void)n_in; (void)out_size;

    // conv: 262144 float4 work items
    conv_kernel<<<(Bn * Pn / 4) / 256, 256>>>((const float4*)features,
                                              conv_w, conv_b, gate);

    for (int k = 0; k < Kn; k++) {
        argmax_kernel<<<Bn, 512>>>(rand_pix, k == 0 ? 1 : 0);
        step_kernel<<<(Bn * Pn) / 256, 256>>>(out, log_sigma,
                                              k, k == 0 ? 1 : 0,
                                              k == Kn - 1 ? 1 : 0);
    }
}

// round 2
// speedup vs baseline: 1.0848x; 1.0848x over previous
#include <cuda_runtime.h>
#include <cstdint>

#define Bn 64
#define Fn 64
#define Cn 8
#define Sn 128
#define Pn (Sn * Sn)          // 16384 pixels per image
#define Kn 10                 // steps_to_run
#define PB 64                 // partial blocks per batch (16384/256)
#define NBLK (Bn * PB)        // 4096 step/partial blocks

// Scratch (device globals: allocation-free per harness rules)
__device__ float g_colour[(size_t)Bn * Cn * Pn];  // [b][c][p]
__device__ float g_logs[(size_t)Bn * Pn];         // [b][p]
__device__ float g_seed[Bn * Cn];                 // [b][c]
__device__ float g_pval[NBLK];                    // per-block argmax partial value
__device__ int   g_pidx[NBLK];                    // per-block argmax partial index

// ---------------------------------------------------------------------------
// Block-level argmax reduce (first-index tie-break), blockDim=256.
// Each thread contributes (v, p) where p ascends with tid.
// ---------------------------------------------------------------------------
__device__ __forceinline__ void block_argmax_256(float v, int p, int blk) {
    // warp reduce
#pragma unroll
    for (int o = 16; o; o >>= 1) {
        float ov = __shfl_down_sync(0xFFFFFFFFu, v, o);
        int   op = __shfl_down_sync(0xFFFFFFFFu, p, o);
        if (ov > v || (ov == v && op < p)) { v = ov; p = op; }
    }
    __shared__ float sv[8];
    __shared__ int   sp[8];
    int tid = threadIdx.x;
    int wid = tid >> 5;
    if ((tid & 31) == 0) { sv[wid] = v; sp[wid] = p; }
    __syncthreads();
    if (tid == 0) {
#pragma unroll
        for (int i = 1; i < 8; i++)
            if (sv[i] > v || (sv[i] == v && sp[i] < p)) { v = sv[i]; p = sp[i]; }
        g_pval[blk] = v;
        g_pidx[blk] = p;
    }
}

// ---------------------------------------------------------------------------
// Kernel 1: 1x1 conv + gate + coordinate channels -> g_colour.
// ---------------------------------------------------------------------------
__global__ void conv_kernel(const float4* __restrict__ feat,
                            const float* __restrict__ w,
                            const float* __restrict__ bias,
                            const float* __restrict__ gate) {
    __shared__ float ws[Cn * Fn];
    __shared__ float bs[Cn];
    int tid = threadIdx.x;
    for (int i = tid; i < Cn * Fn; i += blockDim.x) ws[i] = w[i];
    if (tid < Cn) bs[tid] = bias[tid];
    __syncthreads();

    int gidx = blockIdx.x * blockDim.x + tid;   // 0 .. B*P/4-1
    int b = gidx >> 12;
    int q = gidx & 4095;

    const float4* fb = feat + (size_t)b * (Fn * Pn / 4) + q;

    float4 acc[Cn];
#pragma unroll
    for (int c = 0; c < Cn; c++) {
        float bb = bs[c];
        acc[c] = make_float4(bb, bb, bb, bb);
    }

#pragma unroll 8
    for (int f = 0; f < Fn; f++) {
        float4 v = fb[(size_t)f * (Pn / 4)];
#pragma unroll
        for (int c = 0; c < Cn; c++) {
            float wc = ws[c * Fn + f];
            acc[c].x += v.x * wc;
            acc[c].y += v.y * wc;
            acc[c].z += v.z * wc;
            acc[c].w += v.w * wc;
        }
    }

    float g = gate[0];
#pragma unroll
    for (int c = 0; c < Cn; c++) {
        acc[c].x *= g; acc[c].y *= g; acc[c].z *= g; acc[c].w *= g;
    }

    int p0 = q << 2;
    int h  = p0 >> 7;
    int wc0 = p0 & 127;
    const float step = 2.0f / 127.0f;
    float yy = -1.0f + step * (float)h;
    acc[6].x += yy; acc[6].y += yy; acc[6].z += yy; acc[6].w += yy;
    float xx = -1.0f + step * (float)wc0;
    acc[7].x += xx;
    acc[7].y += xx + step;
    acc[7].z += xx + 2.0f * step;
    acc[7].w += xx + 3.0f * step;

    float4* cb = (float4*)g_colour;
#pragma unroll
    for (int c = 0; c < Cn; c++)
        cb[((size_t)b * Cn + c) * (Pn / 4) + q] = acc[c];
}

// ---------------------------------------------------------------------------
// Kernel 2: initial argmax partials over rand_pixel (step 0 scope == 1).
// 4096 blocks x 256 threads, one pixel per thread.
// ---------------------------------------------------------------------------
__global__ void init_partial_kernel(const float* __restrict__ rp) {
    int idx = blockIdx.x * blockDim.x + threadIdx.x;   // global pixel index
    int p = idx & (Pn - 1);                            // index within batch
    block_argmax_256(rp[idx], p, blockIdx.x);
}

// ---------------------------------------------------------------------------
// Kernel 3: final argmax reduce over PB partials per batch + seed gather.
// 64 blocks x 64 threads.
// ---------------------------------------------------------------------------
__global__ void reduce_seed_kernel() {
    int b = blockIdx.x;
    int tid = threadIdx.x;            // 0..63
    float v = g_pval[b * PB + tid];
    int   p = g_pidx[b * PB + tid];
    int blk = tid;                    // block order ascends with tid
    // tie-break: earlier block wins on equal values (block order == index order)
#pragma unroll
    for (int o = 16; o; o >>= 1) {
        float ov = __shfl_down_sync(0xFFFFFFFFu, v, o);
        int   op = __shfl_down_sync(0xFFFFFFFFu, p, o);
        int   ob = __shfl_down_sync(0xFFFFFFFFu, blk, o);
        if (ov > v || (ov == v && ob < blk)) { v = ov; p = op; blk = ob; }
    }
    __shared__ float sv[2];
    __shared__ int   sp[2];
    __shared__ int   sb[2];
    if ((tid & 31) == 0) { sv[tid >> 5] = v; sp[tid >> 5] = p; sb[tid >> 5] = blk; }
    __syncthreads();
    if (tid == 0) {
        if (sv[1] > v || (sv[1] == v && sb[1] < blk)) { v = sv[1]; p = sp[1]; }
#pragma unroll
        for (int c = 0; c < Cn; c++)
            g_seed[b * Cn + c] = g_colour[((size_t)b * Cn + c) * Pn + p];
    }
}

// ---------------------------------------------------------------------------
// Kernel 4: mask update + fused next-step argmax partials.
// 4096 blocks x 256 threads, one pixel per thread. Block = 256 consecutive
// pixels of one batch.
// ---------------------------------------------------------------------------
__global__ void step_kernel(float* __restrict__ out,
                            const float* __restrict__ rp,
                            const float* __restrict__ log_sigma,
                            int k, int first, int last) {
    int idx = blockIdx.x * blockDim.x + threadIdx.x;  // 0 .. B*P-1
    int b = idx >> 14;
    int p = idx & (Pn - 1);

    float seed[Cn];
#pragma unroll
    for (int c = 0; c < Cn; c++) seed[c] = __ldg(&g_seed[b * Cn + c]);

    float ls = first ? 0.0f : g_logs[idx];

    const float* cb = g_colour + (size_t)b * Cn * Pn + p;
    float d2 = 0.0f;
#pragma unroll
    for (int c = 0; c < Cn; c++) {
        float t = cb[(size_t)c * Pn] - seed[c];
        d2 += t * t;
    }

    float sigma = expf(log_sigma[0]);
    float alpha = expf(-(d2 / sigma));
    alpha = fminf(fmaxf(alpha, 0.01f), 0.99f);

    out[(size_t)idx * (Kn + 1) + k] = ls + logf(alpha);
    ls += logf(1.0f - alpha);

    if (last) {
        out[(size_t)idx * (Kn + 1) + Kn] = ls;
    } else {
        g_logs[idx] = ls;
        // fused argmax partial for next step: v = rand_pixel * exp(log_s)
        float v = rp[idx] * expf(ls);
        block_argmax_256(v, p, blockIdx.x);
    }
}

// ---------------------------------------------------------------------------
extern "C" void kernel_launch(void* const* d_in, const int* in_sizes, int n_in,
                              void* d_out, int out_size) {
    const float* features  = (const float*)d_in[0];
    const float* rand_pix  = (const float*)d_in[1];
    const float* conv_w    = (const float*)d_in[2];
    const float* conv_b    = (const float*)d_in[3];
    const float* gate      = (const float*)d_in[4];
    const float* log_sigma = (const float*)d_in[5];
    float* out = (float*)d_out;

    (void)in_sizes; (void)n_in; (void)out_size;

    conv_kernel<<<(Bn * Pn / 4) / 256, 256>>>((const float4*)features,
                                              conv_w, conv_b, gate);
    init_partial_kernel<<<NBLK, 256>>>(rand_pix);

    for (int k = 0; k < Kn; k++) {
        reduce_seed_kernel<<<Bn, PB>>>();
        step_kernel<<<NBLK, 256>>>(out, rand_pix, log_sigma,
                                   k, k == 0 ? 1 : 0, k == Kn - 1 ? 1 : 0);
    }
}